// round 13
// baseline (speedup 1.0000x reference)
#include <cuda_runtime.h>
#include <math.h>
#include <stdint.h>

#define N_ 512
#define L_ 65536
#define M_ 32768
#define NMOM 32
#define TWO_PI 6.283185307179586f
#define PI_F   3.14159265358979f

// Scratch (allocation-free: __device__ globals)
__device__ float2 d_lamc[N_];    // (lam_re, lam_im)
__device__ float4 d_tA[N_];      // (t0r,t0i,t1r,t1i)
__device__ float4 d_tB[N_];      // (t2r,t2i,t3r,t3i)
__device__ float4 d_mom[NMOM][2];// moments
__device__ float  d_gscale;      // 2/step
__device__ float2 d_atT[L_];     // atRoots transposed: atT[(l&255)*256 + (l>>8)]
__device__ float2 d_stage[M_];   // FFT intermediate
__device__ int    g_mom_ready;   // moments-published counter (reset by prep)
__device__ int    g_bar_count;   // fft grid barrier
__device__ int    g_bar_gen;

__device__ __forceinline__ uint64_t pack2(float lo, float hi) {
    uint64_t r;
    asm("mov.b64 %0, {%1, %2};" : "=l"(r) : "r"(__float_as_uint(lo)), "r"(__float_as_uint(hi)));
    return r;
}
__device__ __forceinline__ void unpack2(uint64_t p, float& lo, float& hi) {
    uint32_t a, b;
    asm("mov.b64 {%0, %1}, %2;" : "=r"(a), "=r"(b) : "l"(p));
    lo = __uint_as_float(a); hi = __uint_as_float(b);
}
__device__ __forceinline__ uint64_t fma2(uint64_t a, uint64_t b, uint64_t c) {
    uint64_t d;
    asm("fma.rn.f32x2 %0, %1, %2, %3;" : "=l"(d) : "l"(a), "l"(b), "l"(c));
    return d;
}
__device__ __forceinline__ uint64_t add2(uint64_t a, uint64_t b) {
    uint64_t d;
    asm("add.rn.f32x2 %0, %1, %2;" : "=l"(d) : "l"(a), "l"(b));
    return d;
}
__device__ __forceinline__ uint64_t mul2(uint64_t a, uint64_t b) {
    uint64_t d;
    asm("mul.rn.f32x2 %0, %1, %2;" : "=l"(d) : "l"(a), "l"(b));
    return d;
}
__device__ __forceinline__ float frcp(float x) {
    float r; asm("rcp.approx.f32 %0, %1;" : "=f"(r) : "f"(x)); return r;
}

// ---------------------------------------------------------------------------
// Kernel 1: Bc = Vc @ B, warp-per-row. Grid 128 x 128 (512 warps = 512 rows,
// single wave). float4 loads, MLP 8/lane, in-warp shfl reduce only.
// ---------------------------------------------------------------------------
__global__ void __launch_bounds__(128) prep_kernel(
        const float* __restrict__ Lre, const float* __restrict__ Lim,
        const float* __restrict__ pre, const float* __restrict__ pim,
        const float* __restrict__ qre, const float* __restrict__ qim,
        const float* __restrict__ Vre, const float* __restrict__ Vim,
        const float* __restrict__ Ct,  const float* __restrict__ B,
        const float* __restrict__ log_step) {
    __shared__ float sB[N_];
    int t = threadIdx.x;
    #pragma unroll
    for (int i = t; i < N_; i += 128) sB[i] = B[i];
    __syncthreads();

    int w = t >> 5, lane = t & 31;
    int j = blockIdx.x * 4 + w;
    const float* vr = Vre + j * N_;
    const float* vi = Vim + j * N_;

    float br = 0.f, bi = 0.f;
    #pragma unroll
    for (int i = 0; i < 4; i++) {
        int idx = lane * 4 + i * 128;
        float4 r4 = *(const float4*)(vr + idx);
        float4 i4 = *(const float4*)(vi + idx);
        float b0 = sB[idx], b1 = sB[idx + 1], b2 = sB[idx + 2], b3 = sB[idx + 3];
        br += r4.x * b0 + r4.y * b1 + r4.z * b2 + r4.w * b3;
        bi += i4.x * b0 + i4.y * b1 + i4.z * b2 + i4.w * b3;
    }
    #pragma unroll
    for (int o = 16; o > 0; o >>= 1) {
        br += __shfl_down_sync(0xffffffffu, br, o);
        bi += __shfl_down_sync(0xffffffffu, bi, o);
    }

    if (lane == 0) {
        float a0r = Ct[2 * j],  a0i = -Ct[2 * j + 1];
        float a1r = qre[j],     a1i = -qim[j];
        float b1r = pre[j],     b1i = pim[j];

        float t0r = a0r * br  - a0i * bi,  t0i = a0r * bi  + a0i * br;
        float t1r = a0r * b1r - a0i * b1i, t1i = a0r * b1i + a0i * b1r;
        float t2r = a1r * br  - a1i * bi,  t2i = a1r * bi  + a1i * br;
        float t3r = a1r * b1r - a1i * b1i, t3i = a1r * b1i + a1i * b1r;

        d_lamc[j] = make_float2(Lre[j], Lim[j]);
        d_tA[j] = make_float4(t0r, t0i, t1r, t1i);
        d_tB[j] = make_float4(t2r, t2i, t3r, t3i);
        if (j == 0) {
            d_gscale = 2.0f / expf(log_step[0]);
            g_mom_ready = 0;   // reset flag for this replay
        }
    }
}

// ---------------------------------------------------------------------------
// Kernel 2: Cauchy -> atRoots (stored TRANSPOSED), moments fused in.
// Block B owns l in [B*128, B*128+128). Near/far per block (R2 from a local
// max-reduce). Blocks 200..231 (always far) each publish one moment first;
// far blocks spin on the counter (hidden behind near-block runtime).
// ---------------------------------------------------------------------------
__global__ void __launch_bounds__(256) cauchy_kernel() {
    __shared__ ulonglong2 sP0[N_];
    __shared__ ulonglong2 sP1[N_];
    __shared__ ulonglong2 sP2[N_];
    __shared__ ulonglong2 sP3[N_];
    __shared__ ulonglong2 sP4[N_];
    __shared__ uint64_t   sLr2[N_];
    __shared__ float4     smom[NMOM][2];
    __shared__ float      sred[8];
    __shared__ float      mred[8][8];

    int t = threadIdx.x, B = blockIdx.x;
    int base = B * 128;
    float gs = d_gscale;

    // Per-block max|lam|^2 reduce -> R2 (no dependence on moments)
    float mx = 0.f;
    #pragma unroll
    for (int i = t; i < N_; i += 256) {
        float2 lam = d_lamc[i];
        mx = fmaxf(mx, lam.x * lam.x + lam.y * lam.y);
    }
    #pragma unroll
    for (int o = 16; o > 0; o >>= 1)
        mx = fmaxf(mx, __shfl_down_sync(0xffffffffu, mx, o));
    if ((t & 31) == 0) sred[t >> 5] = mx;
    __syncthreads();
    float R2 = 2.56f * fmaxf(fmaxf(fmaxf(sred[0], sred[1]), fmaxf(sred[2], sred[3])),
                             fmaxf(fmaxf(sred[4], sred[5]), fmaxf(sred[6], sred[7])));

    // Near test at interval endpoints (|tan| monotone per side of L/2)
    bool nearB;
    {
        float s, c;
        sincosf(PI_F * ((float)base * (1.0f / (float)L_)), &s, &c);
        float ya = gs * __fdividef(s, c);
        sincosf(PI_F * ((float)(base + 127) * (1.0f / (float)L_)), &s, &c);
        float yb = gs * __fdividef(s, c);
        nearB = (ya * ya < R2) || (yb * yb < R2);
    }

    // Moment duty: blocks 200..231 compute moment m = B-200 and publish.
    if (B >= 200 && B < 200 + NMOM) {
        int m = B - 200;
        float acc[8] = {0.f, 0.f, 0.f, 0.f, 0.f, 0.f, 0.f, 0.f};
        #pragma unroll
        for (int i = 0; i < 2; i++) {
            int j = t + 256 * i;
            float2 lam = d_lamc[j];
            float4 tA = d_tA[j];
            float4 tB = d_tB[j];
            float pr = 1.f, pi = 0.f, br = lam.x, bi = lam.y;
            int e = m;
            while (e) {
                if (e & 1) { float nr = pr * br - pi * bi; pi = pr * bi + pi * br; pr = nr; }
                float b2 = br * br - bi * bi; bi = 2.f * br * bi; br = b2;
                e >>= 1;
            }
            acc[0] += tA.x * pr - tA.y * pi;  acc[1] += tA.x * pi + tA.y * pr;
            acc[2] += tA.z * pr - tA.w * pi;  acc[3] += tA.z * pi + tA.w * pr;
            acc[4] += tB.x * pr - tB.y * pi;  acc[5] += tB.x * pi + tB.y * pr;
            acc[6] += tB.z * pr - tB.w * pi;  acc[7] += tB.z * pi + tB.w * pr;
        }
        #pragma unroll
        for (int o = 16; o > 0; o >>= 1)
            #pragma unroll
            for (int k = 0; k < 8; k++)
                acc[k] += __shfl_down_sync(0xffffffffu, acc[k], o);
        if ((t & 31) == 0)
            #pragma unroll
            for (int k = 0; k < 8; k++) mred[t >> 5][k] = acc[k];
        __syncthreads();
        if (t == 0) {
            float r[8];
            #pragma unroll
            for (int k = 0; k < 8; k++) {
                r[k] = 0.f;
                #pragma unroll
                for (int w = 0; w < 8; w++) r[k] += mred[w][k];
            }
            d_mom[m][0] = make_float4(r[0], r[1], r[2], r[3]);
            d_mom[m][1] = make_float4(r[4], r[5], r[6], r[7]);
            __threadfence();
            atomicAdd(&g_mom_ready, 1);
        }
    }

    if (nearB) {
        // ---- exact path: fill duplicated smem tables from compact gmem ----
        #pragma unroll
        for (int i = t; i < N_; i += 256) {
            float2 lam = d_lamc[i];
            float4 tA = d_tA[i];
            float4 tB = d_tB[i];
            ulonglong2 v;
            v.x = pack2(-lam.y, -lam.y); v.y = pack2(-lam.x, -lam.x); sP0[i] = v;
            v.x = pack2(tA.x, tA.x);     v.y = pack2(tA.y, tA.y);     sP1[i] = v;
            v.x = pack2(tA.z, tA.z);     v.y = pack2(tA.w, tA.w);     sP2[i] = v;
            v.x = pack2(tB.x, tB.x);     v.y = pack2(tB.y, tB.y);     sP3[i] = v;
            v.x = pack2(tB.z, tB.z);     v.y = pack2(tB.w, tB.w);     sP4[i] = v;
            sLr2[i] = pack2(lam.x * lam.x, lam.x * lam.x);
        }
        __syncthreads();

        int p = t & 63, chunk = t >> 6;
        int l0 = base + p, l1 = l0 + 64;
        float tan0, tan1;
        {
            float s, c;
            sincosf(PI_F * ((float)l0 * (1.0f / (float)L_)), &s, &c);
            tan0 = __fdividef(s, c);
            sincosf(PI_F * ((float)l1 * (1.0f / (float)L_)), &s, &c);
            tan1 = __fdividef(s, c);
        }
        uint64_t gi2 = pack2(gs * tan0, gs * tan1);

        uint64_t c00r = 0, c00i = 0, c01r = 0, c01i = 0;
        uint64_t c10r = 0, c10i = 0, c11r = 0, c11i = 0;
        const uint64_t SGN2 = 0x8000000080000000ull;

        int jbeg = chunk * 128, jend = jbeg + 128;
        #pragma unroll 4
        for (int j = jbeg; j < jend; j++) {
            ulonglong2 P0 = sP0[j];
            ulonglong2 P1 = sP1[j];
            ulonglong2 P2 = sP2[j];
            ulonglong2 P3 = sP3[j];
            ulonglong2 P4 = sP4[j];
            uint64_t lr2 = sLr2[j];
            uint64_t di2   = add2(gi2, P0.x);
            uint64_t n2    = fma2(di2, di2, lr2);
            float nlo, nhi;
            unpack2(n2, nlo, nhi);
            uint64_t rinv2 = pack2(frcp(nlo), frcp(nhi));
            uint64_t rr2   = mul2(P0.y, rinv2);
            uint64_t m2    = mul2(di2, rinv2);
            uint64_t nm2   = m2 ^ SGN2;

            c00r = fma2(rr2, P1.x, c00r);  c00r = fma2(m2,  P1.y, c00r);
            c00i = fma2(rr2, P1.y, c00i);  c00i = fma2(nm2, P1.x, c00i);
            c01r = fma2(rr2, P2.x, c01r);  c01r = fma2(m2,  P2.y, c01r);
            c01i = fma2(rr2, P2.y, c01i);  c01i = fma2(nm2, P2.x, c01i);
            c10r = fma2(rr2, P3.x, c10r);  c10r = fma2(m2,  P3.y, c10r);
            c10i = fma2(rr2, P3.y, c10i);  c10i = fma2(nm2, P3.x, c10i);
            c11r = fma2(rr2, P4.x, c11r);  c11r = fma2(m2,  P4.y, c11r);
            c11i = fma2(rr2, P4.y, c11i);  c11i = fma2(nm2, P4.x, c11i);
        }

        // Reduce across j-chunks (tables no longer needed -> reuse as scratch)
        __syncthreads();
        if (chunk) {
            uint64_t* area = (chunk == 1) ? (uint64_t*)sP0
                           : (chunk == 2) ? (uint64_t*)sP1 : (uint64_t*)sP2;
            area[p * 8 + 0] = c00r; area[p * 8 + 1] = c00i;
            area[p * 8 + 2] = c01r; area[p * 8 + 3] = c01i;
            area[p * 8 + 4] = c10r; area[p * 8 + 5] = c10i;
            area[p * 8 + 6] = c11r; area[p * 8 + 7] = c11i;
        }
        __syncthreads();
        if (chunk == 0) {
            const uint64_t* a1p = (const uint64_t*)sP0;
            const uint64_t* a2p = (const uint64_t*)sP1;
            const uint64_t* a3p = (const uint64_t*)sP2;
            c00r = add2(add2(c00r, a1p[p*8+0]), add2(a2p[p*8+0], a3p[p*8+0]));
            c00i = add2(add2(c00i, a1p[p*8+1]), add2(a2p[p*8+1], a3p[p*8+1]));
            c01r = add2(add2(c01r, a1p[p*8+2]), add2(a2p[p*8+2], a3p[p*8+2]));
            c01i = add2(add2(c01i, a1p[p*8+3]), add2(a2p[p*8+3], a3p[p*8+3]));
            c10r = add2(add2(c10r, a1p[p*8+4]), add2(a2p[p*8+4], a3p[p*8+4]));
            c10i = add2(add2(c10i, a1p[p*8+5]), add2(a2p[p*8+5], a3p[p*8+5]));
            c11r = add2(add2(c11r, a1p[p*8+6]), add2(a2p[p*8+6], a3p[p*8+6]));
            c11i = add2(add2(c11i, a1p[p*8+7]), add2(a2p[p*8+7], a3p[p*8+7]));

            float k00r[2], k00i[2], k01r[2], k01i[2], k10r[2], k10i[2], k11r[2], k11i[2];
            unpack2(c00r, k00r[0], k00r[1]); unpack2(c00i, k00i[0], k00i[1]);
            unpack2(c01r, k01r[0], k01r[1]); unpack2(c01i, k01i[0], k01i[1]);
            unpack2(c10r, k10r[0], k10r[1]); unpack2(c10i, k10i[0], k10i[1]);
            unpack2(c11r, k11r[0], k11r[1]); unpack2(c11i, k11i[0], k11i[1]);
            float tn[2] = {tan0, tan1};
            #pragma unroll
            for (int u = 0; u < 2; u++) {
                int l = u ? l1 : l0;
                float ddr = 1.f + k11r[u], ddi = k11i[u];
                float dinv = __fdividef(1.f, ddr * ddr + ddi * ddi);
                float qr = k01r[u] * k10r[u] - k01i[u] * k10i[u];
                float qi = k01r[u] * k10i[u] + k01i[u] * k10r[u];
                float qdr = (qr * ddr + qi * ddi) * dinv;
                float qdi = (qi * ddr - qr * ddi) * dinv;
                float ar = k00r[u] - qdr;
                float ai = k00i[u] - qdi;
                float tv = tn[u];
                d_atT[(l & 255) * 256 + (l >> 8)] =
                    make_float2(ar - tv * ai, ai + tv * ar);
            }
        }
    } else {
        // ---- far path: wait for moments, then scalar Horner in w = -i/y ----
        if (t == 0) {
            while (*(volatile int*)&g_mom_ready < NMOM) { }
            __threadfence();
        }
        __syncthreads();
        if (t < NMOM * 2) ((float4*)smom)[t] = ((const float4*)d_mom)[t];
        __syncthreads();

        if (t < 128) {
            int l = base + t;
            float s, c;
            sincosf(PI_F * ((float)l * (1.0f / (float)L_)), &s, &c);
            float tv = __fdividef(s, c);
            float y = gs * tv;
            float uu = frcp(y);

            float4 A = smom[NMOM - 1][0], Bm = smom[NMOM - 1][1];
            float h0r = A.x,  h0i = A.y,  h1r = A.z,  h1i = A.w;
            float h2r = Bm.x, h2i = Bm.y, h3r = Bm.z, h3i = Bm.w;
            #pragma unroll
            for (int m = NMOM - 2; m >= 0; m--) {
                float4 A2 = smom[m][0], B2 = smom[m][1];
                float n0r = fmaf(h0i, uu, A2.x), n0i = fmaf(-h0r, uu, A2.y);
                float n1r = fmaf(h1i, uu, A2.z), n1i = fmaf(-h1r, uu, A2.w);
                float n2r = fmaf(h2i, uu, B2.x), n2i = fmaf(-h2r, uu, B2.y);
                float n3r = fmaf(h3i, uu, B2.z), n3i = fmaf(-h3r, uu, B2.w);
                h0r = n0r; h0i = n0i; h1r = n1r; h1i = n1i;
                h2r = n2r; h2i = n2i; h3r = n3r; h3i = n3i;
            }
            float k00r = h0i * uu,  k00i = -h0r * uu;
            float k01r = h1i * uu,  k01i = -h1r * uu;
            float k10r = h2i * uu,  k10i = -h2r * uu;
            float k11r = h3i * uu,  k11i = -h3r * uu;

            float ddr = 1.f + k11r, ddi = k11i;
            float dinv = __fdividef(1.f, ddr * ddr + ddi * ddi);
            float qr = k01r * k10r - k01i * k10i;
            float qi = k01r * k10i + k01i * k10r;
            float qdr = (qr * ddr + qi * ddi) * dinv;
            float qdi = (qi * ddr - qr * ddi) * dinv;
            float ar = k00r - qdr;
            float ai = k00i - qdi;
            d_atT[(l & 255) * 256 + (l >> 8)] =
                make_float2(ar - tv * ai, ai + tv * ar);
        }
    }
}

// ---------------------------------------------------------------------------
// Kernel 3: fused real-IFFT (both four-step stages), persistent grid 128x256
// with a software grid barrier (all 128 blocks co-resident on 148 SMs).
// Phase 1 (per half-block, a = 2*blk + h):
//   G[k] = (X[k]+conj(X[L-k]))(1+i w_k) + (X[k+M]+conj(X[M-k]))(1-i w_k)
//   then 128-pt DFT over t (radix 16x8), twiddle W_M^{a c}, transpose-store.
// Phase 2 (whole block, column c = blk): 256-pt DFT (radix 16x16), output.
// ---------------------------------------------------------------------------
__global__ void __launch_bounds__(256) fft_fused(float2* __restrict__ out) {
    __shared__ float2 sw1[128];        // e^{+2pi i k/128}
    __shared__ float2 sA[2][256];
    __shared__ float2 sR[2][256];
    __shared__ float2 sg[2][128];
    __shared__ float2 sz1[2][16 * 9];
    __shared__ float2 sx[256];
    __shared__ float2 sw2[256];        // e^{+2pi i k/256}
    __shared__ float2 sz2[16 * 17];

    int blk = blockIdx.x, t = threadIdx.x;
    int h = t >> 7, r = t & 127;
    int a = 2 * blk + h;
    int ra = (256 - a) & 255;

    // ---- Phase 1 ----
    {
        float4 vA = *(const float4*)(&d_atT[a * 256 + 2 * r]);
        float4 vR = *(const float4*)(&d_atT[ra * 256 + 2 * r]);
        sA[h][2 * r]     = make_float2(vA.x, vA.y);
        sA[h][2 * r + 1] = make_float2(vA.z, vA.w);
        sR[h][2 * r]     = make_float2(vR.x, vR.y);
        sR[h][2 * r + 1] = make_float2(vR.z, vR.w);
        if (h == 0) {
            float s, c;
            __sincosf(TWO_PI * ((float)r * (1.0f / 128.0f)), &s, &c);
            sw1[r] = make_float2(c, s);
        }
    }
    __syncthreads();

    // Build G[a + 256 r]
    {
        int k1 = a + 256 * r;
        int i2 = (L_ - k1) & (L_ - 1);
        int i4 = M_ - k1;
        float2 X1 = sA[h][r];
        float2 X2 = sR[h][i2 >> 8];
        float2 X3 = sA[h][r + 128];
        float2 X4 = sR[h][i4 >> 8];
        float Ar = X1.x + X2.x, Ai = X1.y - X2.y;
        float Br = X3.x + X4.x, Bi = X3.y - X4.y;
        float ws, wc;
        __sincosf(TWO_PI * ((float)k1 * (1.0f / (float)L_)), &ws, &wc);
        float Qr = Ar - Br, Qi = Ai - Bi;
        float wqr = wc * Qr - ws * Qi;
        float wqi = wc * Qi + ws * Qr;
        sg[h][r] = make_float2(Ar + Br - wqi, Ai + Bi + wqr);
    }
    __syncthreads();

    // Stage A: z[b1][c1] over b2 in [0,8)
    {
        int b1 = r & 15, c1 = r >> 4;
        float xr = 0.f, xi = 0.f;
        #pragma unroll
        for (int b2 = 0; b2 < 8; b2++) {
            float2 x = sg[h][b1 + 16 * b2];
            float2 w = sw1[(16 * b2 * c1) & 127];
            xr += x.x * w.x - x.y * w.y;
            xi += x.x * w.y + x.y * w.x;
        }
        float2 tw = sw1[(b1 * c1) & 127];
        sz1[h][b1 * 9 + c1] = make_float2(xr * tw.x - xi * tw.y,
                                          xr * tw.y + xi * tw.x);
    }
    __syncthreads();

    // Stage B: S[c1 + 8 c2], output index r; twiddle W_M^{a r}; transpose-store
    {
        int c1 = r & 7, c2 = r >> 3;
        float yr = 0.f, yi = 0.f;
        #pragma unroll
        for (int b1 = 0; b1 < 16; b1++) {
            float2 z = sz1[h][b1 * 9 + c1];
            float2 w = sw1[(8 * b1 * c2) & 127];
            yr += z.x * w.x - z.y * w.y;
            yi += z.x * w.y + z.y * w.x;
        }
        int m = (a * r) & (M_ - 1);
        float ws, wc;
        __sincosf(TWO_PI * ((float)m * (1.0f / (float)M_)), &ws, &wc);
        d_stage[r * 256 + a] = make_float2(yr * wc - yi * ws,
                                           yr * ws + yi * wc);
    }

    // ---- Grid barrier (all 128 blocks resident) ----
    __threadfence();
    __syncthreads();
    if (t == 0) {
        int gen = *(volatile int*)&g_bar_gen;
        if (atomicAdd(&g_bar_count, 1) == 127) {
            g_bar_count = 0;
            __threadfence();
            *(volatile int*)&g_bar_gen = gen + 1;
        } else {
            while (*(volatile int*)&g_bar_gen == gen) { }
        }
        __threadfence();
    }
    __syncthreads();

    // ---- Phase 2: column c = blk, 256 threads ----
    int c = blk;
    sx[t] = d_stage[c * 256 + t];
    {
        float s, cc;
        __sincosf(TWO_PI * ((float)t * (1.0f / 256.0f)), &s, &cc);
        sw2[t] = make_float2(cc, s);
    }
    __syncthreads();

    {
        int a1 = t & 15, d1 = t >> 4;
        float xr = 0.f, xi = 0.f;
        #pragma unroll
        for (int a2 = 0; a2 < 16; a2++) {
            float2 x = sx[a1 + 16 * a2];
            float2 w = sw2[(16 * a2 * d1) & 255];
            xr += x.x * w.x - x.y * w.y;
            xi += x.x * w.y + x.y * w.x;
        }
        float2 tw = sw2[a1 * d1];
        sz2[a1 * 17 + d1] = make_float2(xr * tw.x - xi * tw.y,
                                        xr * tw.y + xi * tw.x);
    }
    __syncthreads();

    {
        int d1 = t & 15, d2 = t >> 4;
        float yr = 0.f, yi = 0.f;
        #pragma unroll
        for (int a1 = 0; a1 < 16; a1++) {
            float2 z = sz2[a1 * 17 + d1];
            float2 w = sw2[(16 * a1 * d2) & 255];
            yr += z.x * w.x - z.y * w.y;
            yi += z.x * w.y + z.y * w.x;
        }
        const float sc = 1.0f / (2.0f * (float)L_);
        out[c + 128 * t] = make_float2(yr * sc, yi * sc);
    }
}

// ---------------------------------------------------------------------------
extern "C" void kernel_launch(void* const* d_in, const int* in_sizes, int n_in,
                              void* d_out, int out_size) {
    const float* Lambda_re = (const float*)d_in[0];
    const float* Lambda_im = (const float*)d_in[1];
    const float* p_re      = (const float*)d_in[2];
    const float* p_im      = (const float*)d_in[3];
    const float* q_re      = (const float*)d_in[4];
    const float* q_im      = (const float*)d_in[5];
    const float* Vc_re     = (const float*)d_in[6];
    const float* Vc_im     = (const float*)d_in[7];
    const float* Ct        = (const float*)d_in[8];
    const float* B         = (const float*)d_in[9];
    const float* log_step  = (const float*)d_in[10];

    prep_kernel<<<128, 128>>>(Lambda_re, Lambda_im, p_re, p_im, q_re, q_im,
                              Vc_re, Vc_im, Ct, B, log_step);
    cauchy_kernel<<<512, 256>>>();
    fft_fused<<<128, 256>>>((float2*)d_out);
}

// round 14
// speedup vs baseline: 1.0106x; 1.0106x over previous
#include <cuda_runtime.h>
#include <math.h>
#include <stdint.h>

#define N_ 512
#define L_ 65536
#define M_ 32768
#define NMOM 32
#define TWO_PI 6.283185307179586f
#define PI_F   3.14159265358979f

// Scratch (allocation-free: __device__ globals)
__device__ float4 d_tA[N_];      // (t0r,t0i,t1r,t1i)
__device__ float4 d_tB[N_];      // (t2r,t2i,t3r,t3i)
__device__ float4 d_mom[NMOM][2];// moments
__device__ float2 d_atT[L_];     // atRoots transposed: atT[(l&255)*256 + (l>>8)]
__device__ float2 d_stage[M_];   // FFT intermediate
__device__ int    g_gemv_ready;  // GEMV rows published (reset by fft)
__device__ int    g_mom_ready;   // moments published  (reset by fft)
__device__ int    g_bar_count;   // fft grid barrier
__device__ int    g_bar_gen;

__device__ __forceinline__ uint64_t pack2(float lo, float hi) {
    uint64_t r;
    asm("mov.b64 %0, {%1, %2};" : "=l"(r) : "r"(__float_as_uint(lo)), "r"(__float_as_uint(hi)));
    return r;
}
__device__ __forceinline__ void unpack2(uint64_t p, float& lo, float& hi) {
    uint32_t a, b;
    asm("mov.b64 {%0, %1}, %2;" : "=r"(a), "=r"(b) : "l"(p));
    lo = __uint_as_float(a); hi = __uint_as_float(b);
}
__device__ __forceinline__ uint64_t fma2(uint64_t a, uint64_t b, uint64_t c) {
    uint64_t d;
    asm("fma.rn.f32x2 %0, %1, %2, %3;" : "=l"(d) : "l"(a), "l"(b), "l"(c));
    return d;
}
__device__ __forceinline__ uint64_t add2(uint64_t a, uint64_t b) {
    uint64_t d;
    asm("add.rn.f32x2 %0, %1, %2;" : "=l"(d) : "l"(a), "l"(b));
    return d;
}
__device__ __forceinline__ uint64_t mul2(uint64_t a, uint64_t b) {
    uint64_t d;
    asm("mul.rn.f32x2 %0, %1, %2;" : "=l"(d) : "l"(a), "l"(b));
    return d;
}
__device__ __forceinline__ float frcp(float x) {
    float r; asm("rcp.approx.f32 %0, %1;" : "=f"(r) : "f"(x)); return r;
}

// ---------------------------------------------------------------------------
// Kernel 1 (fused prep+cauchy): 256 co-resident blocks, 2 tiles each.
// Phase 0: each block computes 2 GEMV rows -> d_tA/d_tB, grid-spin.
// Phase 1: moments (blocks 200..231, always-far tiles), near/far per tile.
// ---------------------------------------------------------------------------
__global__ void __launch_bounds__(256, 2) cauchy_kernel(
        const float* __restrict__ Lre, const float* __restrict__ Lim,
        const float* __restrict__ pre, const float* __restrict__ pim,
        const float* __restrict__ qre, const float* __restrict__ qim,
        const float* __restrict__ Vre, const float* __restrict__ Vim,
        const float* __restrict__ Ct,  const float* __restrict__ Bp,
        const float* __restrict__ log_step) {
    __shared__ ulonglong2 sP0[N_];
    __shared__ ulonglong2 sP1[N_];
    __shared__ ulonglong2 sP2[N_];
    __shared__ ulonglong2 sP3[N_];
    __shared__ ulonglong2 sP4[N_];
    __shared__ uint64_t   sLr2[N_];
    __shared__ float4     smom[NMOM][2];
    __shared__ float      sBv[N_];
    __shared__ float      sgr[8], sgi[8];
    __shared__ float      sred[8];
    __shared__ float      mred[8][8];

    int t = threadIdx.x, B = blockIdx.x;
    float gs = 2.0f / expf(log_step[0]);

    // ---- Phase 0: GEMV rows j = 2B, 2B+1 ----
    #pragma unroll
    for (int i = t; i < N_; i += 256) sBv[i] = Bp[i];
    __syncthreads();
    {
        int half = t >> 7, rt = t & 127;
        int j = 2 * B + half;
        float4 r4 = ((const float4*)(Vre + j * N_))[rt];
        float4 i4 = ((const float4*)(Vim + j * N_))[rt];
        float b0 = sBv[4 * rt], b1 = sBv[4 * rt + 1];
        float b2 = sBv[4 * rt + 2], b3 = sBv[4 * rt + 3];
        float br = r4.x * b0 + r4.y * b1 + r4.z * b2 + r4.w * b3;
        float bi = i4.x * b0 + i4.y * b1 + i4.z * b2 + i4.w * b3;
        #pragma unroll
        for (int o = 16; o > 0; o >>= 1) {
            br += __shfl_down_sync(0xffffffffu, br, o);
            bi += __shfl_down_sync(0xffffffffu, bi, o);
        }
        if ((t & 31) == 0) { sgr[t >> 5] = br; sgi[t >> 5] = bi; }
        __syncthreads();
        if (rt == 0) {
            float Bcr = sgr[4*half] + sgr[4*half+1] + sgr[4*half+2] + sgr[4*half+3];
            float Bci = sgi[4*half] + sgi[4*half+1] + sgi[4*half+2] + sgi[4*half+3];
            float a0r = Ct[2 * j],  a0i = -Ct[2 * j + 1];
            float a1r = qre[j],     a1i = -qim[j];
            float b1r = pre[j],     b1i = pim[j];
            d_tA[j] = make_float4(a0r * Bcr - a0i * Bci, a0r * Bci + a0i * Bcr,
                                  a0r * b1r - a0i * b1i, a0r * b1i + a0i * b1r);
            d_tB[j] = make_float4(a1r * Bcr - a1i * Bci, a1r * Bci + a1i * Bcr,
                                  a1r * b1r - a1i * b1i, a1r * b1i + a1i * b1r);
        }
        __syncthreads();
        if (t == 0) { __threadfence(); atomicAdd(&g_gemv_ready, 1); }
    }

    // ---- R2 from inputs (independent of GEMV) ----
    float mx = 0.f;
    #pragma unroll
    for (int i = t; i < N_; i += 256) {
        float lr = Lre[i], li = Lim[i];
        mx = fmaxf(mx, lr * lr + li * li);
    }
    #pragma unroll
    for (int o = 16; o > 0; o >>= 1)
        mx = fmaxf(mx, __shfl_down_sync(0xffffffffu, mx, o));
    if ((t & 31) == 0) sred[t >> 5] = mx;
    __syncthreads();
    float R2 = 2.56f * fmaxf(fmaxf(fmaxf(sred[0], sred[1]), fmaxf(sred[2], sred[3])),
                             fmaxf(fmaxf(sred[4], sred[5]), fmaxf(sred[6], sred[7])));

    // ---- Wait for all GEMV rows ----
    if (t == 0) {
        while (*(volatile int*)&g_gemv_ready < 256) { }
        __threadfence();
    }
    __syncthreads();

    // ---- Moment duty: blocks 200..231 (tiles 200 & 456 are always far) ----
    if (B >= 200 && B < 200 + NMOM) {
        int m = B - 200;
        float acc[8] = {0.f, 0.f, 0.f, 0.f, 0.f, 0.f, 0.f, 0.f};
        #pragma unroll
        for (int i = 0; i < 2; i++) {
            int j = t + 256 * i;
            float lr = Lre[j], li = Lim[j];
            float4 tA = d_tA[j];
            float4 tB = d_tB[j];
            float pr = 1.f, pi = 0.f, br = lr, bi = li;
            int e = m;
            while (e) {
                if (e & 1) { float nr = pr * br - pi * bi; pi = pr * bi + pi * br; pr = nr; }
                float b2 = br * br - bi * bi; bi = 2.f * br * bi; br = b2;
                e >>= 1;
            }
            acc[0] += tA.x * pr - tA.y * pi;  acc[1] += tA.x * pi + tA.y * pr;
            acc[2] += tA.z * pr - tA.w * pi;  acc[3] += tA.z * pi + tA.w * pr;
            acc[4] += tB.x * pr - tB.y * pi;  acc[5] += tB.x * pi + tB.y * pr;
            acc[6] += tB.z * pr - tB.w * pi;  acc[7] += tB.z * pi + tB.w * pr;
        }
        #pragma unroll
        for (int o = 16; o > 0; o >>= 1)
            #pragma unroll
            for (int k = 0; k < 8; k++)
                acc[k] += __shfl_down_sync(0xffffffffu, acc[k], o);
        if ((t & 31) == 0)
            #pragma unroll
            for (int k = 0; k < 8; k++) mred[t >> 5][k] = acc[k];
        __syncthreads();
        if (t == 0) {
            float r[8];
            #pragma unroll
            for (int k = 0; k < 8; k++) {
                r[k] = 0.f;
                #pragma unroll
                for (int w = 0; w < 8; w++) r[k] += mred[w][k];
            }
            d_mom[m][0] = make_float4(r[0], r[1], r[2], r[3]);
            d_mom[m][1] = make_float4(r[4], r[5], r[6], r[7]);
            __threadfence();
            atomicAdd(&g_mom_ready, 1);
        }
    }

    // ---- Two tiles per block: T = B and B+256 ----
    bool tablesFilled = false;
    bool momLoaded = false;
    #pragma unroll
    for (int tt = 0; tt < 2; tt++) {
        int tile = B + 256 * tt;
        int base = tile * 128;

        bool nearB;
        {
            float s, c;
            sincosf(PI_F * ((float)base * (1.0f / (float)L_)), &s, &c);
            float ya = gs * __fdividef(s, c);
            sincosf(PI_F * ((float)(base + 127) * (1.0f / (float)L_)), &s, &c);
            float yb = gs * __fdividef(s, c);
            nearB = (ya * ya < R2) || (yb * yb < R2);
        }

        if (nearB) {
            if (!tablesFilled) {
                __syncthreads();
                #pragma unroll
                for (int i = t; i < N_; i += 256) {
                    float lr = Lre[i], li = Lim[i];
                    float4 tA = d_tA[i];
                    float4 tB = d_tB[i];
                    ulonglong2 v;
                    v.x = pack2(-li, -li);   v.y = pack2(-lr, -lr);   sP0[i] = v;
                    v.x = pack2(tA.x, tA.x); v.y = pack2(tA.y, tA.y); sP1[i] = v;
                    v.x = pack2(tA.z, tA.z); v.y = pack2(tA.w, tA.w); sP2[i] = v;
                    v.x = pack2(tB.x, tB.x); v.y = pack2(tB.y, tB.y); sP3[i] = v;
                    v.x = pack2(tB.z, tB.z); v.y = pack2(tB.w, tB.w); sP4[i] = v;
                    sLr2[i] = pack2(lr * lr, lr * lr);
                }
                __syncthreads();
                tablesFilled = true;
            }

            int p = t & 63, chunk = t >> 6;
            int l0 = base + p, l1 = l0 + 64;
            float tan0, tan1;
            {
                float s, c;
                sincosf(PI_F * ((float)l0 * (1.0f / (float)L_)), &s, &c);
                tan0 = __fdividef(s, c);
                sincosf(PI_F * ((float)l1 * (1.0f / (float)L_)), &s, &c);
                tan1 = __fdividef(s, c);
            }
            uint64_t gi2 = pack2(gs * tan0, gs * tan1);

            uint64_t c00r = 0, c00i = 0, c01r = 0, c01i = 0;
            uint64_t c10r = 0, c10i = 0, c11r = 0, c11i = 0;
            const uint64_t SGN2 = 0x8000000080000000ull;

            int jbeg = chunk * 128, jend = jbeg + 128;
            #pragma unroll 4
            for (int j = jbeg; j < jend; j++) {
                ulonglong2 P0 = sP0[j];
                ulonglong2 P1 = sP1[j];
                ulonglong2 P2 = sP2[j];
                ulonglong2 P3 = sP3[j];
                ulonglong2 P4 = sP4[j];
                uint64_t lr2 = sLr2[j];
                uint64_t di2   = add2(gi2, P0.x);
                uint64_t n2    = fma2(di2, di2, lr2);
                float nlo, nhi;
                unpack2(n2, nlo, nhi);
                uint64_t rinv2 = pack2(frcp(nlo), frcp(nhi));
                uint64_t rr2   = mul2(P0.y, rinv2);
                uint64_t m2    = mul2(di2, rinv2);
                uint64_t nm2   = m2 ^ SGN2;

                c00r = fma2(rr2, P1.x, c00r);  c00r = fma2(m2,  P1.y, c00r);
                c00i = fma2(rr2, P1.y, c00i);  c00i = fma2(nm2, P1.x, c00i);
                c01r = fma2(rr2, P2.x, c01r);  c01r = fma2(m2,  P2.y, c01r);
                c01i = fma2(rr2, P2.y, c01i);  c01i = fma2(nm2, P2.x, c01i);
                c10r = fma2(rr2, P3.x, c10r);  c10r = fma2(m2,  P3.y, c10r);
                c10i = fma2(rr2, P3.y, c10i);  c10i = fma2(nm2, P3.x, c10i);
                c11r = fma2(rr2, P4.x, c11r);  c11r = fma2(m2,  P4.y, c11r);
                c11i = fma2(rr2, P4.y, c11i);  c11i = fma2(nm2, P4.x, c11i);
            }

            // Reduce across j-chunks (scratch overwrites tables)
            __syncthreads();
            if (chunk) {
                uint64_t* area = (chunk == 1) ? (uint64_t*)sP0
                               : (chunk == 2) ? (uint64_t*)sP1 : (uint64_t*)sP2;
                area[p * 8 + 0] = c00r; area[p * 8 + 1] = c00i;
                area[p * 8 + 2] = c01r; area[p * 8 + 3] = c01i;
                area[p * 8 + 4] = c10r; area[p * 8 + 5] = c10i;
                area[p * 8 + 6] = c11r; area[p * 8 + 7] = c11i;
            }
            __syncthreads();
            if (chunk == 0) {
                const uint64_t* a1p = (const uint64_t*)sP0;
                const uint64_t* a2p = (const uint64_t*)sP1;
                const uint64_t* a3p = (const uint64_t*)sP2;
                c00r = add2(add2(c00r, a1p[p*8+0]), add2(a2p[p*8+0], a3p[p*8+0]));
                c00i = add2(add2(c00i, a1p[p*8+1]), add2(a2p[p*8+1], a3p[p*8+1]));
                c01r = add2(add2(c01r, a1p[p*8+2]), add2(a2p[p*8+2], a3p[p*8+2]));
                c01i = add2(add2(c01i, a1p[p*8+3]), add2(a2p[p*8+3], a3p[p*8+3]));
                c10r = add2(add2(c10r, a1p[p*8+4]), add2(a2p[p*8+4], a3p[p*8+4]));
                c10i = add2(add2(c10i, a1p[p*8+5]), add2(a2p[p*8+5], a3p[p*8+5]));
                c11r = add2(add2(c11r, a1p[p*8+6]), add2(a2p[p*8+6], a3p[p*8+6]));
                c11i = add2(add2(c11i, a1p[p*8+7]), add2(a2p[p*8+7], a3p[p*8+7]));

                float k00r[2], k00i[2], k01r[2], k01i[2], k10r[2], k10i[2], k11r[2], k11i[2];
                unpack2(c00r, k00r[0], k00r[1]); unpack2(c00i, k00i[0], k00i[1]);
                unpack2(c01r, k01r[0], k01r[1]); unpack2(c01i, k01i[0], k01i[1]);
                unpack2(c10r, k10r[0], k10r[1]); unpack2(c10i, k10i[0], k10i[1]);
                unpack2(c11r, k11r[0], k11r[1]); unpack2(c11i, k11i[0], k11i[1]);
                float tn[2] = {tan0, tan1};
                #pragma unroll
                for (int u = 0; u < 2; u++) {
                    int l = u ? l1 : l0;
                    float ddr = 1.f + k11r[u], ddi = k11i[u];
                    float dinv = __fdividef(1.f, ddr * ddr + ddi * ddi);
                    float qr = k01r[u] * k10r[u] - k01i[u] * k10i[u];
                    float qi = k01r[u] * k10i[u] + k01i[u] * k10r[u];
                    float qdr = (qr * ddr + qi * ddi) * dinv;
                    float qdi = (qi * ddr - qr * ddi) * dinv;
                    float ar = k00r[u] - qdr;
                    float ai = k00i[u] - qdi;
                    float tv = tn[u];
                    d_atT[(l & 255) * 256 + (l >> 8)] =
                        make_float2(ar - tv * ai, ai + tv * ar);
                }
            }
            tablesFilled = false;  // scratch destroyed tables
        } else {
            // ---- far path: wait moments, Horner in w = -i/y ----
            if (!momLoaded) {
                if (t == 0) {
                    while (*(volatile int*)&g_mom_ready < NMOM) { }
                    __threadfence();
                }
                __syncthreads();
                if (t < NMOM * 2) ((float4*)smom)[t] = ((const float4*)d_mom)[t];
                __syncthreads();
                momLoaded = true;
            }

            if (t < 128) {
                int l = base + t;
                float s, c;
                sincosf(PI_F * ((float)l * (1.0f / (float)L_)), &s, &c);
                float tv = __fdividef(s, c);
                float y = gs * tv;
                float uu = frcp(y);

                float4 A = smom[NMOM - 1][0], Bm = smom[NMOM - 1][1];
                float h0r = A.x,  h0i = A.y,  h1r = A.z,  h1i = A.w;
                float h2r = Bm.x, h2i = Bm.y, h3r = Bm.z, h3i = Bm.w;
                #pragma unroll
                for (int m = NMOM - 2; m >= 0; m--) {
                    float4 A2 = smom[m][0], B2 = smom[m][1];
                    float n0r = fmaf(h0i, uu, A2.x), n0i = fmaf(-h0r, uu, A2.y);
                    float n1r = fmaf(h1i, uu, A2.z), n1i = fmaf(-h1r, uu, A2.w);
                    float n2r = fmaf(h2i, uu, B2.x), n2i = fmaf(-h2r, uu, B2.y);
                    float n3r = fmaf(h3i, uu, B2.z), n3i = fmaf(-h3r, uu, B2.w);
                    h0r = n0r; h0i = n0i; h1r = n1r; h1i = n1i;
                    h2r = n2r; h2i = n2i; h3r = n3r; h3i = n3i;
                }
                float k00r = h0i * uu,  k00i = -h0r * uu;
                float k01r = h1i * uu,  k01i = -h1r * uu;
                float k10r = h2i * uu,  k10i = -h2r * uu;
                float k11r = h3i * uu,  k11i = -h3r * uu;

                float ddr = 1.f + k11r, ddi = k11i;
                float dinv = __fdividef(1.f, ddr * ddr + ddi * ddi);
                float qr = k01r * k10r - k01i * k10i;
                float qi = k01r * k10i + k01i * k10r;
                float qdr = (qr * ddr + qi * ddi) * dinv;
                float qdi = (qi * ddr - qr * ddi) * dinv;
                float ar = k00r - qdr;
                float ai = k00i - qdi;
                d_atT[(l & 255) * 256 + (l >> 8)] =
                    make_float2(ar - tv * ai, ai + tv * ar);
            }
        }
    }
}

// ---------------------------------------------------------------------------
// Kernel 2: fused real-IFFT (both four-step stages), persistent grid 128x256
// with a software grid barrier (all 128 blocks co-resident).
// Also resets the cauchy counters for the next graph replay.
// ---------------------------------------------------------------------------
__global__ void __launch_bounds__(256) fft_fused(float2* __restrict__ out) {
    __shared__ float2 sw1[128];
    __shared__ float2 sA[2][256];
    __shared__ float2 sR[2][256];
    __shared__ float2 sg[2][128];
    __shared__ float2 sz1[2][16 * 9];
    __shared__ float2 sx[256];
    __shared__ float2 sw2[256];
    __shared__ float2 sz2[16 * 17];

    int blk = blockIdx.x, t = threadIdx.x;
    if (blk == 0 && t == 0) { g_gemv_ready = 0; g_mom_ready = 0; }

    int h = t >> 7, r = t & 127;
    int a = 2 * blk + h;
    int ra = (256 - a) & 255;

    // ---- Phase 1 ----
    {
        float4 vA = *(const float4*)(&d_atT[a * 256 + 2 * r]);
        float4 vR = *(const float4*)(&d_atT[ra * 256 + 2 * r]);
        sA[h][2 * r]     = make_float2(vA.x, vA.y);
        sA[h][2 * r + 1] = make_float2(vA.z, vA.w);
        sR[h][2 * r]     = make_float2(vR.x, vR.y);
        sR[h][2 * r + 1] = make_float2(vR.z, vR.w);
        if (h == 0) {
            float s, c;
            __sincosf(TWO_PI * ((float)r * (1.0f / 128.0f)), &s, &c);
            sw1[r] = make_float2(c, s);
        }
    }
    __syncthreads();

    {
        int k1 = a + 256 * r;
        int i2 = (L_ - k1) & (L_ - 1);
        int i4 = M_ - k1;
        float2 X1 = sA[h][r];
        float2 X2 = sR[h][i2 >> 8];
        float2 X3 = sA[h][r + 128];
        float2 X4 = sR[h][i4 >> 8];
        float Ar = X1.x + X2.x, Ai = X1.y - X2.y;
        float Br = X3.x + X4.x, Bi = X3.y - X4.y;
        float ws, wc;
        __sincosf(TWO_PI * ((float)k1 * (1.0f / (float)L_)), &ws, &wc);
        float Qr = Ar - Br, Qi = Ai - Bi;
        float wqr = wc * Qr - ws * Qi;
        float wqi = wc * Qi + ws * Qr;
        sg[h][r] = make_float2(Ar + Br - wqi, Ai + Bi + wqr);
    }
    __syncthreads();

    {
        int b1 = r & 15, c1 = r >> 4;
        float xr = 0.f, xi = 0.f;
        #pragma unroll
        for (int b2 = 0; b2 < 8; b2++) {
            float2 x = sg[h][b1 + 16 * b2];
            float2 w = sw1[(16 * b2 * c1) & 127];
            xr += x.x * w.x - x.y * w.y;
            xi += x.x * w.y + x.y * w.x;
        }
        float2 tw = sw1[(b1 * c1) & 127];
        sz1[h][b1 * 9 + c1] = make_float2(xr * tw.x - xi * tw.y,
                                          xr * tw.y + xi * tw.x);
    }
    __syncthreads();

    {
        int c1 = r & 7, c2 = r >> 3;
        float yr = 0.f, yi = 0.f;
        #pragma unroll
        for (int b1 = 0; b1 < 16; b1++) {
            float2 z = sz1[h][b1 * 9 + c1];
            float2 w = sw1[(8 * b1 * c2) & 127];
            yr += z.x * w.x - z.y * w.y;
            yi += z.x * w.y + z.y * w.x;
        }
        int m = (a * r) & (M_ - 1);
        float ws, wc;
        __sincosf(TWO_PI * ((float)m * (1.0f / (float)M_)), &ws, &wc);
        d_stage[r * 256 + a] = make_float2(yr * wc - yi * ws,
                                           yr * ws + yi * wc);
    }

    // ---- Grid barrier ----
    __threadfence();
    __syncthreads();
    if (t == 0) {
        int gen = *(volatile int*)&g_bar_gen;
        if (atomicAdd(&g_bar_count, 1) == 127) {
            g_bar_count = 0;
            __threadfence();
            *(volatile int*)&g_bar_gen = gen + 1;
        } else {
            while (*(volatile int*)&g_bar_gen == gen) { }
        }
        __threadfence();
    }
    __syncthreads();

    // ---- Phase 2 ----
    int c = blk;
    sx[t] = d_stage[c * 256 + t];
    {
        float s, cc;
        __sincosf(TWO_PI * ((float)t * (1.0f / 256.0f)), &s, &cc);
        sw2[t] = make_float2(cc, s);
    }
    __syncthreads();

    {
        int a1 = t & 15, d1 = t >> 4;
        float xr = 0.f, xi = 0.f;
        #pragma unroll
        for (int a2 = 0; a2 < 16; a2++) {
            float2 x = sx[a1 + 16 * a2];
            float2 w = sw2[(16 * a2 * d1) & 255];
            xr += x.x * w.x - x.y * w.y;
            xi += x.x * w.y + x.y * w.x;
        }
        float2 tw = sw2[a1 * d1];
        sz2[a1 * 17 + d1] = make_float2(xr * tw.x - xi * tw.y,
                                        xr * tw.y + xi * tw.x);
    }
    __syncthreads();

    {
        int d1 = t & 15, d2 = t >> 4;
        float yr = 0.f, yi = 0.f;
        #pragma unroll
        for (int a1 = 0; a1 < 16; a1++) {
            float2 z = sz2[a1 * 17 + d1];
            float2 w = sw2[(16 * a1 * d2) & 255];
            yr += z.x * w.x - z.y * w.y;
            yi += z.x * w.y + z.y * w.x;
        }
        const float sc = 1.0f / (2.0f * (float)L_);
        out[c + 128 * t] = make_float2(yr * sc, yi * sc);
    }
}

// ---------------------------------------------------------------------------
extern "C" void kernel_launch(void* const* d_in, const int* in_sizes, int n_in,
                              void* d_out, int out_size) {
    const float* Lambda_re = (const float*)d_in[0];
    const float* Lambda_im = (const float*)d_in[1];
    const float* p_re      = (const float*)d_in[2];
    const float* p_im      = (const float*)d_in[3];
    const float* q_re      = (const float*)d_in[4];
    const float* q_im      = (const float*)d_in[5];
    const float* Vc_re     = (const float*)d_in[6];
    const float* Vc_im     = (const float*)d_in[7];
    const float* Ct        = (const float*)d_in[8];
    const float* B         = (const float*)d_in[9];
    const float* log_step  = (const float*)d_in[10];

    cauchy_kernel<<<256, 256>>>(Lambda_re, Lambda_im, p_re, p_im, q_re, q_im,
                                Vc_re, Vc_im, Ct, B, log_step);
    fft_fused<<<128, 256>>>((float2*)d_out);
}